// round 4
// baseline (speedup 1.0000x reference)
#include <cuda_runtime.h>
#include <cuda_bf16.h>
#include <cstdint>

// Problem constants (fixed by the reference setup_inputs)
constexpr int T_STEPS = 2048;
constexpr int BATCH   = 8192;
constexpr int CHUNK   = 16;                  // timesteps per pipeline stage
constexpr int NCHUNK  = T_STEPS / CHUNK;     // 128
constexpr int STAGES  = 4;                   // cp.async smem ring depth
constexpr int EPB     = 32;                  // elements per block
constexpr int TPB     = 128;                 // w0:n0  w1:n1  w2:out  w3:loader

// Izhikevich params (regular spiking)
#define IZH_A   0.02f
#define IZH_B   0.2f
#define IZH_C   (-65.0f)
#define IZH_D   8.0f
#define IZH_VTH 30.0f

__device__ __forceinline__ void cp_async16(void* smem_dst, const void* gmem_src) {
    uint32_t s = (uint32_t)__cvta_generic_to_shared(smem_dst);
    asm volatile("cp.async.cg.shared.global [%0], [%1], 16;\n" :: "r"(s), "l"(gmem_src) : "memory");
}
__device__ __forceinline__ void cp_commit() {
    asm volatile("cp.async.commit_group;\n" ::: "memory");
}
__device__ __forceinline__ void cp_wait2() {
    asm volatile("cp.async.wait_group 2;\n" ::: "memory");
}

__global__ __launch_bounds__(TPB) void snn_izh_pipe_kernel(
    const float4* __restrict__ xs,     // [T, B] float4 (F_IN = 4)
    const float*  __restrict__ W_in,   // [2,4]
    const float*  __restrict__ b_in,   // [2]
    const float*  __restrict__ W_out,  // [1,2]
    const float*  __restrict__ b_out,  // [1]
    float*        __restrict__ out)    // [T, B]
{
    // xs staging ring: 4 stages x 16 steps x 32 elements x float4 = 32 KB
    __shared__ float4 ring[STAGES][CHUNK][EPB];
    // spike double-buffer: [buf][step][neuron][lane] = 8 KB
    __shared__ float zbuf[2][CHUNK][2][EPB];

    const int wid  = threadIdx.x >> 5;
    const int lane = threadIdx.x & 31;
    const int elem = blockIdx.x * EPB + lane;

    if (wid == 3) {
        // ─────────── LOADER warp: cp.async pipeline, 3 chunks ahead ───────────
        const float4* xp = xs + elem;   // stride BATCH between timesteps

        // prologue: stages 0,1,2 as 3 groups
        #pragma unroll
        for (int s = 0; s < STAGES - 1; s++) {
            #pragma unroll
            for (int k = 0; k < CHUNK; k++)
                cp_async16(&ring[s][k][lane], xp + (size_t)(s * CHUNK + k) * BATCH);
            cp_commit();
        }
        cp_wait2();          // stage 0 complete
        __syncthreads();     // visible to all; invariant: at chunk c, stage c ready

        #pragma unroll 1
        for (int c = 0; c <= NCHUNK; c++) {
            const int ls = c + STAGES - 1;          // stage to issue
            if (ls < NCHUNK) {
                const int slot = ls & (STAGES - 1);
                #pragma unroll
                for (int k = 0; k < CHUNK; k++)
                    cp_async16(&ring[slot][k][lane], xp + (size_t)(ls * CHUNK + k) * BATCH);
            }
            cp_commit();     // empty group at tail keeps wait_group<2> uniform
            cp_wait2();      // stage c+1 complete (for next chunk)
            __syncthreads();
        }
    } else if (wid < 2) {
        // ─────────── HIDDEN warp (one neuron per warp) ───────────
        const int n = wid;
        const float w0 = W_in[n * 4 + 0];
        const float w1 = W_in[n * 4 + 1];
        const float w2 = W_in[n * 4 + 2];
        const float w3 = W_in[n * 4 + 3];
        const float bi = b_in[n];

        float v = IZH_C, u = IZH_B * IZH_C;

        __syncthreads();     // pairs with loader prologue barrier

        #pragma unroll 1
        for (int c = 0; c <= NCHUNK; c++) {
            if (c < NCHUNK) {
                const int slot = c & (STAGES - 1);
                const int cb   = c & 1;
                #pragma unroll
                for (int k = 0; k < CHUNK; k++) {
                    const float4 x = ring[slot][k][lane];

                    // input linear (frozen expression order — bit-exact vs reference)
                    const float h = w0 * x.x + w1 * x.y + w2 * x.z + w3 * x.w + bi;

                    // Izhikevich step (frozen order)
                    v = v + (0.04f * v * v + 5.0f * v + 140.0f - u + h);
                    u = u + IZH_A * (IZH_B * v - u);
                    const bool p = (v >= IZH_VTH);
                    const float z = p ? 1.0f : 0.0f;
                    v = p ? IZH_C : v;
                    u = p ? (u + IZH_D) : u;   // exact: fma(z,D,u), z in {0,1}

                    zbuf[cb][k][n][lane] = z;
                }
            }
            __syncthreads();
        }
    } else {
        // ─────────── OUTPUT warp (lags one chunk) ───────────
        const float wo0 = W_out[0], wo1 = W_out[1];
        const float bo  = b_out[0];

        float v = IZH_C, u = IZH_B * IZH_C;
        float* op = out + elem;

        __syncthreads();     // pairs with loader prologue barrier

        #pragma unroll 1
        for (int c = 0; c <= NCHUNK; c++) {
            if (c > 0) {
                const int cb    = (c - 1) & 1;
                const int tbase = (c - 1) * CHUNK;
                #pragma unroll
                for (int k = 0; k < CHUNK; k++) {
                    const float z0 = zbuf[cb][k][0][lane];
                    const float z1 = zbuf[cb][k][1][lane];

                    const float y = z0 * wo0 + z1 * wo1 + bo;

                    v = v + (0.04f * v * v + 5.0f * v + 140.0f - u + y);
                    u = u + IZH_A * (IZH_B * v - u);
                    const bool p = (v >= IZH_VTH);
                    const float z2 = p ? 1.0f : 0.0f;
                    v = p ? IZH_C : v;
                    u = p ? (u + IZH_D) : u;

                    op[(size_t)(tbase + k) * BATCH] = z2;
                }
            }
            __syncthreads();
        }
    }
}

extern "C" void kernel_launch(void* const* d_in, const int* in_sizes, int n_in,
                              void* d_out, int out_size) {
    const float4* xs    = (const float4*)d_in[0];
    const float*  W_in  = (const float*)d_in[1];
    const float*  b_in  = (const float*)d_in[2];
    const float*  W_out = (const float*)d_in[3];
    const float*  b_out = (const float*)d_in[4];
    float* out = (float*)d_out;

    dim3 grid(BATCH / EPB);   // 256 blocks
    dim3 block(TPB);          // 4 warps: n0 / n1 / output / loader
    snn_izh_pipe_kernel<<<grid, block>>>(xs, W_in, b_in, W_out, b_out, out);
}

// round 5
// speedup vs baseline: 1.8607x; 1.8607x over previous
#include <cuda_runtime.h>
#include <cuda_bf16.h>
#include <cstdint>

// Problem constants (fixed by the reference setup_inputs)
constexpr int T_STEPS = 2048;
constexpr int BATCH   = 8192;
constexpr int CHUNK   = 16;                  // timesteps per pipeline stage
constexpr int NCHUNK  = T_STEPS / CHUNK;     // 128
constexpr int STAGES  = 4;                   // x staging ring depth
constexpr int EPB     = 32;                  // elements per block
constexpr int TPB     = 96;                  // w0: hidden n0+loads, w1: hidden n1+loads, w2: output
constexpr int HALF    = CHUNK / 2;           // steps loaded per hidden warp per chunk

// Izhikevich params (regular spiking)
#define IZH_A   0.02f
#define IZH_B   0.2f
#define IZH_C   (-65.0f)
#define IZH_D   8.0f
#define IZH_VTH 30.0f

__device__ __forceinline__ void cp_async16(void* smem_dst, const void* gmem_src) {
    uint32_t s = (uint32_t)__cvta_generic_to_shared(smem_dst);
    asm volatile("cp.async.cg.shared.global [%0], [%1], 16;\n" :: "r"(s), "l"(gmem_src) : "memory");
}
__device__ __forceinline__ void cp_commit() {
    asm volatile("cp.async.commit_group;\n" ::: "memory");
}
__device__ __forceinline__ void cp_wait2() {
    asm volatile("cp.async.wait_group 2;\n" ::: "memory");
}

// The reference polynomial, FROZEN source expression (bit-exact vs reference).
__device__ __forceinline__ float izh_poly(float v, float u, float I) {
    return v + (0.04f * v * v + 5.0f * v + 140.0f - u + I);
}

__global__ __launch_bounds__(TPB) void snn_izh_spec_kernel(
    const float4* __restrict__ xs,     // [T, B] float4 (F_IN = 4)
    const float*  __restrict__ W_in,   // [2,4]
    const float*  __restrict__ b_in,   // [2]
    const float*  __restrict__ W_out,  // [1,2]
    const float*  __restrict__ b_out,  // [1]
    float*        __restrict__ out)    // [T, B]
{
    // x staging ring: 4 stages x 16 steps x 32 lanes x float4 = 32 KB
    __shared__ float4 xring[STAGES][CHUNK][EPB];
    // packed spike double-buffer: [buf][neuron][group-of-4-steps][lane] = 8 KB
    __shared__ float4 zbuf[2][2][CHUNK / 4][EPB];

    const int wid  = threadIdx.x >> 5;
    const int lane = threadIdx.x & 31;
    const int elem = blockIdx.x * EPB + lane;

    // Opaque C: forces the spike-path poly to compile as the same runtime
    // FMUL/FFMA/FADD sequence as the general path (no constant folding).
    float Cop = IZH_C;
    asm volatile("" : "+f"(Cop));

    if (wid < 2) {
        // ───── HIDDEN warp: owns neuron n, loads half of each chunk ─────
        const int n = wid;
        const float w0 = W_in[n * 4 + 0];
        const float w1 = W_in[n * 4 + 1];
        const float w2 = W_in[n * 4 + 2];
        const float w3 = W_in[n * 4 + 3];
        const float bi = b_in[n];

        const float4* xp = xs + elem;          // stride BATCH between timesteps
        const int soff = n * HALF;             // this warp's half of every chunk

        // prologue: stage s holds chunk s; issue stages 0..2 (3 groups)
        #pragma unroll
        for (int s = 0; s < STAGES - 1; s++) {
            #pragma unroll
            for (int k = 0; k < HALF; k++)
                cp_async16(&xring[s][soff + k][lane],
                           xp + (size_t)(s * CHUNK + soff + k) * BATCH);
            cp_commit();
        }

        // speculative state: vn = pre-reset v of prev step, up = u' (pre +D), p = prev spike
        float vn = IZH_C;            // with p=false this acts as v_sel = C initial state
        float up = IZH_B * IZH_C;
        bool  p  = false;

        #pragma unroll 1
        for (int c = 0; c <= NCHUNK; c++) {
            if (c < NCHUNK) cp_wait2();   // group c (stage c) complete
            __syncthreads();              // publish x stage c cross-warp; zbuf handoff
            if (c < NCHUNK) {
                const int slot = c & (STAGES - 1);
                const int cb   = c & 1;
                float4 zq;
                #pragma unroll
                for (int k = 0; k < CHUNK; k++) {
                    const float4 x = xring[slot][k][lane];
                    // input linear (frozen order)
                    const float h = w0 * x.x + w1 * x.y + w2 * x.z + w3 * x.w + bi;

                    // speculative Izhikevich step (both reset paths, select on prev p)
                    const float uB = up + IZH_D;              // == fma(z=1, D, u')
                    const float pA = izh_poly(vn,  up, h);    // no-spike path
                    const float pB = izh_poly(Cop, uB, h);    // spike path (same ops)
                    const float vnn  = p ? pB : pA;
                    const float usel = p ? uB : up;
                    up = usel + IZH_A * (IZH_B * vnn - usel); // frozen order
                    p  = (vnn >= IZH_VTH);
                    vn = vnn;
                    const float z = p ? 1.0f : 0.0f;

                    // pack 4 steps per STS.128 (keeps barrier STS-drain cheap)
                    if      ((k & 3) == 0) zq.x = z;
                    else if ((k & 3) == 1) zq.y = z;
                    else if ((k & 3) == 2) zq.z = z;
                    else { zq.w = z; zbuf[cb][n][k >> 2][lane] = zq; }
                }
                // issue stage c+3 (or empty group to keep the FIFO count uniform)
                const int ls = c + STAGES - 1;
                if (ls < NCHUNK) {
                    const int lslot = ls & (STAGES - 1);
                    #pragma unroll
                    for (int k = 0; k < HALF; k++)
                        cp_async16(&xring[lslot][soff + k][lane],
                                   xp + (size_t)(ls * CHUNK + soff + k) * BATCH);
                }
                cp_commit();
            }
        }
    } else {
        // ───── OUTPUT warp (lags one chunk) ─────
        const float wo0 = W_out[0], wo1 = W_out[1];
        const float bo  = b_out[0];

        float vn = IZH_C;
        float up = IZH_B * IZH_C;
        bool  p  = false;
        float* op = out + elem;

        #pragma unroll 1
        for (int c = 0; c <= NCHUNK; c++) {
            __syncthreads();
            if (c > 0) {
                const int cb    = (c - 1) & 1;
                const int tbase = (c - 1) * CHUNK;
                #pragma unroll
                for (int g = 0; g < CHUNK / 4; g++) {
                    const float4 z0q = zbuf[cb][0][g][lane];
                    const float4 z1q = zbuf[cb][1][g][lane];
                    #pragma unroll
                    for (int j = 0; j < 4; j++) {
                        const float z0 = (j == 0) ? z0q.x : (j == 1) ? z0q.y : (j == 2) ? z0q.z : z0q.w;
                        const float z1 = (j == 0) ? z1q.x : (j == 1) ? z1q.y : (j == 2) ? z1q.z : z1q.w;

                        // output linear (frozen order)
                        const float y = z0 * wo0 + z1 * wo1 + bo;

                        const float uB = up + IZH_D;
                        const float pA = izh_poly(vn,  up, y);
                        const float pB = izh_poly(Cop, uB, y);
                        const float vnn  = p ? pB : pA;
                        const float usel = p ? uB : up;
                        up = usel + IZH_A * (IZH_B * vnn - usel);
                        p  = (vnn >= IZH_VTH);
                        vn = vnn;
                        const float z2 = p ? 1.0f : 0.0f;

                        op[(size_t)(tbase + g * 4 + j) * BATCH] = z2;
                    }
                }
            }
        }
    }
}

extern "C" void kernel_launch(void* const* d_in, const int* in_sizes, int n_in,
                              void* d_out, int out_size) {
    const float4* xs    = (const float4*)d_in[0];
    const float*  W_in  = (const float*)d_in[1];
    const float*  b_in  = (const float*)d_in[2];
    const float*  W_out = (const float*)d_in[3];
    const float*  b_out = (const float*)d_in[4];
    float* out = (float*)d_out;

    dim3 grid(BATCH / EPB);   // 256 blocks
    dim3 block(TPB);          // 3 warps: hidden n0 / hidden n1 / output
    snn_izh_spec_kernel<<<grid, block>>>(xs, W_in, b_in, W_out, b_out, out);
}

// round 6
// speedup vs baseline: 1.9902x; 1.0696x over previous
#include <cuda_runtime.h>
#include <cuda_bf16.h>
#include <cstdint>

// Problem constants (fixed by the reference setup_inputs)
constexpr int T_STEPS = 2048;
constexpr int BATCH   = 8192;
constexpr int CHUNK   = 32;                  // timesteps per pipeline stage
constexpr int NCHUNK  = T_STEPS / CHUNK;     // 64
constexpr int STAGES  = 3;                   // x staging ring depth
constexpr int EPB     = 32;                  // elements per block
constexpr int TPB     = 96;                  // w0: hidden n0+loads, w1: hidden n1+loads, w2: output
constexpr int HALF    = CHUNK / 2;           // steps loaded per hidden warp per chunk

// Izhikevich params (regular spiking)
#define IZH_A   0.02f
#define IZH_B   0.2f
#define IZH_C   (-65.0f)
#define IZH_D   8.0f
#define IZH_VTH 30.0f

__device__ __forceinline__ void cp_async16(void* smem_dst, const void* gmem_src) {
    uint32_t s = (uint32_t)__cvta_generic_to_shared(smem_dst);
    asm volatile("cp.async.cg.shared.global [%0], [%1], 16;\n" :: "r"(s), "l"(gmem_src) : "memory");
}
__device__ __forceinline__ void cp_commit() {
    asm volatile("cp.async.commit_group;\n" ::: "memory");
}
__device__ __forceinline__ void cp_wait1() {
    asm volatile("cp.async.wait_group 1;\n" ::: "memory");
}

// The reference polynomial, FROZEN source expression (bit-exact vs reference).
__device__ __forceinline__ float izh_poly(float v, float u, float I) {
    return v + (0.04f * v * v + 5.0f * v + 140.0f - u + I);
}

__global__ __launch_bounds__(TPB) void snn_izh_spec32_kernel(
    const float4* __restrict__ xs,     // [T, B] float4 (F_IN = 4)
    const float*  __restrict__ W_in,   // [2,4]
    const float*  __restrict__ b_in,   // [2]
    const float*  __restrict__ W_out,  // [1,2]
    const float*  __restrict__ b_out,  // [1]
    float*        __restrict__ out)    // [T, B]
{
    // x staging ring: 3 stages x 32 steps x 32 lanes x float4 = 48 KB
    __shared__ float4 xring[STAGES][CHUNK][EPB];
    // packed spike double-buffer: [buf][neuron][group-of-4-steps][lane] = 16 KB
    __shared__ float4 zbuf[2][2][CHUNK / 4][EPB];

    const int wid  = threadIdx.x >> 5;
    const int lane = threadIdx.x & 31;
    const int elem = blockIdx.x * EPB + lane;

    // Opaque C: forces the spike-path poly to compile as the same runtime
    // FMUL/FFMA/FADD sequence as the general path (no constant folding).
    float Cop = IZH_C;
    asm volatile("" : "+f"(Cop));

    if (wid < 2) {
        // ───── HIDDEN warp: owns neuron n, loads half of each chunk ─────
        const int n = wid;
        const float w0 = W_in[n * 4 + 0];
        const float w1 = W_in[n * 4 + 1];
        const float w2 = W_in[n * 4 + 2];
        const float w3 = W_in[n * 4 + 3];
        const float bi = b_in[n];

        const float4* xp = xs + elem;          // stride BATCH between timesteps
        const int soff = n * HALF;             // this warp's half of every chunk

        // prologue: stage s holds chunk s; issue stages 0..1 (2 groups)
        #pragma unroll
        for (int s = 0; s < STAGES - 1; s++) {
            #pragma unroll
            for (int k = 0; k < HALF; k++)
                cp_async16(&xring[s][soff + k][lane],
                           xp + (size_t)(s * CHUNK + soff + k) * BATCH);
            cp_commit();
        }

        // speculative state: vn = pre-reset v of prev step, up = u' (pre +D), p = prev spike
        float vn = IZH_C;            // with p=false this acts as v_sel = C initial state
        float up = IZH_B * IZH_C;
        bool  p  = false;

        #pragma unroll 1
        for (int c = 0; c <= NCHUNK; c++) {
            if (c < NCHUNK) cp_wait1();   // oldest in-flight group (stage c) complete
            __syncthreads();              // publish x stage c cross-warp; zbuf handoff
            if (c < NCHUNK) {
                // Issue stage c+2 FIRST so the loads overlap this chunk's compute.
                const int ls = c + STAGES - 1;
                if (ls < NCHUNK) {
                    const int lslot = ls % STAGES;
                    #pragma unroll
                    for (int k = 0; k < HALF; k++)
                        cp_async16(&xring[lslot][soff + k][lane],
                                   xp + (size_t)(ls * CHUNK + soff + k) * BATCH);
                }
                cp_commit();   // empty group at the tail keeps FIFO count uniform

                const int slot = c % STAGES;
                const int cb   = c & 1;
                float4 zq;
                #pragma unroll
                for (int k = 0; k < CHUNK; k++) {
                    const float4 x = xring[slot][k][lane];
                    // input linear (frozen order)
                    const float h = w0 * x.x + w1 * x.y + w2 * x.z + w3 * x.w + bi;

                    // speculative Izhikevich step (both reset paths, select on prev p)
                    const float uB = up + IZH_D;              // == fma(z=1, D, u')
                    const float pA = izh_poly(vn,  up, h);    // no-spike path
                    const float pB = izh_poly(Cop, uB, h);    // spike path (same ops)
                    const float vnn  = p ? pB : pA;
                    const float usel = p ? uB : up;
                    up = usel + IZH_A * (IZH_B * vnn - usel); // frozen order
                    p  = (vnn >= IZH_VTH);
                    vn = vnn;
                    const float z = p ? 1.0f : 0.0f;

                    // pack 4 steps per STS.128 (keeps barrier STS-drain cheap)
                    if      ((k & 3) == 0) zq.x = z;
                    else if ((k & 3) == 1) zq.y = z;
                    else if ((k & 3) == 2) zq.z = z;
                    else { zq.w = z; zbuf[cb][n][k >> 2][lane] = zq; }
                }
            }
        }
    } else {
        // ───── OUTPUT warp (lags one chunk) ─────
        const float wo0 = W_out[0], wo1 = W_out[1];
        const float bo  = b_out[0];

        float vn = IZH_C;
        float up = IZH_B * IZH_C;
        bool  p  = false;
        float* op = out + elem;

        #pragma unroll 1
        for (int c = 0; c <= NCHUNK; c++) {
            __syncthreads();
            if (c > 0) {
                const int cb    = (c - 1) & 1;
                const int tbase = (c - 1) * CHUNK;
                #pragma unroll
                for (int g = 0; g < CHUNK / 4; g++) {
                    const float4 z0q = zbuf[cb][0][g][lane];
                    const float4 z1q = zbuf[cb][1][g][lane];
                    #pragma unroll
                    for (int j = 0; j < 4; j++) {
                        const float z0 = (j == 0) ? z0q.x : (j == 1) ? z0q.y : (j == 2) ? z0q.z : z0q.w;
                        const float z1 = (j == 0) ? z1q.x : (j == 1) ? z1q.y : (j == 2) ? z1q.z : z1q.w;

                        // output linear (frozen order)
                        const float y = z0 * wo0 + z1 * wo1 + bo;

                        const float uB = up + IZH_D;
                        const float pA = izh_poly(vn,  up, y);
                        const float pB = izh_poly(Cop, uB, y);
                        const float vnn  = p ? pB : pA;
                        const float usel = p ? uB : up;
                        up = usel + IZH_A * (IZH_B * vnn - usel);
                        p  = (vnn >= IZH_VTH);
                        vn = vnn;
                        const float z2 = p ? 1.0f : 0.0f;

                        op[(size_t)(tbase + g * 4 + j) * BATCH] = z2;
                    }
                }
            }
        }
    }
}

extern "C" void kernel_launch(void* const* d_in, const int* in_sizes, int n_in,
                              void* d_out, int out_size) {
    const float4* xs    = (const float4*)d_in[0];
    const float*  W_in  = (const float*)d_in[1];
    const float*  b_in  = (const float*)d_in[2];
    const float*  W_out = (const float*)d_in[3];
    const float*  b_out = (const float*)d_in[4];
    float* out = (float*)d_out;

    dim3 grid(BATCH / EPB);   // 256 blocks
    dim3 block(TPB);          // 3 warps: hidden n0 / hidden n1 / output
    snn_izh_spec32_kernel<<<grid, block>>>(xs, W_in, b_in, W_out, b_out, out);
}